// round 15
// baseline (speedup 1.0000x reference)
#include <cuda_runtime.h>
#include <cuda_fp16.h>

#define B_     32
#define N_     577
#define L_     576
#define DIM_   512
#define HEADS_ 8
#define NDIM_  16
#define M_ROWS (B_ * N_)   // 18464
#define ECH 32             // EMA chunks
#define ECL 18             // chunk length (32*18 = 576)
#define EDL 8              // channels per CTA
#define VTP 640            // padded j-extent of V^T

// -------- scratch (device globals; __half arrays 16B-aligned for cp.async) --------
// RULE: NEVER pass these as host-side kernel arguments (host shadow symbol!).
__device__ __align__(16) __half g_xm16[(size_t)B_ * N_ * DIM_];
__device__ __align__(16) __half g_qk16[(size_t)B_ * N_ * 1024];
__device__ float g_v [(size_t)B_ * N_ * 512];
__device__ __align__(16) __half g_vt16[(size_t)B_ * 512 * VTP];
__device__ __align__(16) __half g_ao16[(size_t)B_ * N_ * 512];
__device__ float g_cq[NDIM_][2 * DIM_];
__device__ float g_cc[NDIM_][2 * DIM_];
__device__ __align__(16) __half g_wqk16[1024 * 512];
__device__ __align__(16) __half g_wv16 [512 * 512];
__device__ __align__(16) __half g_wo16 [512 * 512];

// ---------------- helpers ----------------
__device__ __forceinline__ unsigned f2tf(float x) {
    unsigned u;
    asm("cvt.rna.tf32.f32 %0, %1;" : "=r"(u) : "f"(x));
    return u;
}
__device__ __forceinline__ float f2tff(float x) { return __uint_as_float(f2tf(x)); }
__device__ __forceinline__ unsigned pack2(float x, float y) {
    __half2 h = __floats2half2_rn(x, y);
    return *reinterpret_cast<unsigned*>(&h);
}
__device__ __forceinline__ void mma16(float* c, const unsigned* a, unsigned b0, unsigned b1) {
    asm volatile(
        "mma.sync.aligned.m16n8k16.row.col.f32.f16.f16.f32 "
        "{%0,%1,%2,%3},{%4,%5,%6,%7},{%8,%9},{%0,%1,%2,%3};"
        : "+f"(c[0]), "+f"(c[1]), "+f"(c[2]), "+f"(c[3])
        : "r"(a[0]), "r"(a[1]), "r"(a[2]), "r"(a[3]), "r"(b0), "r"(b1));
}
__device__ __forceinline__ unsigned s2u(const void* p) {
    return (unsigned)__cvta_generic_to_shared(p);
}
__device__ __forceinline__ void cp16(unsigned dst, const void* src, int srcsz) {
    asm volatile("cp.async.cg.shared.global [%0], [%1], 16, %2;"
                 :: "r"(dst), "l"(src), "r"(srcsz));
}
#define CP_COMMIT() asm volatile("cp.async.commit_group;")
#define CP_WAIT1()  asm volatile("cp.async.wait_group 1;")

__device__ __forceinline__ float pow18f(float q) {
    float q2 = q * q, q4 = q2 * q2, q8 = q4 * q4, q16 = q8 * q8;
    return q16 * q2;
}

// ================= Stage 0: EMA coefficients + fused weight prep =================
__global__ void coef_kernel(const float* __restrict__ delta, const float* __restrict__ alpha,
                            const float* __restrict__ beta,  const float* __restrict__ gamma) {
    int idx = blockIdx.x * blockDim.x + threadIdx.x;
    if (idx >= 2 * DIM_ * NDIM_) return;
    int d = idx / NDIM_;
    int n = idx % NDIM_;
    float p  = 1.f / (1.f + expf(-delta[idx]));
    float sa = 1.f / (1.f + expf(-alpha[idx]));
    g_cq[n][d] = 1.f - p * sa;
    g_cc[n][d] = p * beta[idx] * gamma[idx] * 0.25f;
}

// One launch converts all three weights.  i in [0, 1024*512 + 2*512*512)
__global__ void tcvt_all(const float* __restrict__ wqk, const float* __restrict__ wv,
                         const float* __restrict__ wo) {
    int i = blockIdx.x * 256 + threadIdx.x;
    if (i < 1024 * 512) {
        int n = i >> 9, k = i & 511;
        g_wqk16[i] = __float2half_rn(wqk[(size_t)k * 1024 + n]);
    } else if (i < 1024 * 512 + 512 * 512) {
        int j = i - 1024 * 512;
        int n = j >> 9, k = j & 511;
        g_wv16[j] = __float2half_rn(wv[(size_t)k * 512 + n]);
    } else if (i < 1024 * 512 + 2 * 512 * 512) {
        int j = i - 1024 * 512 - 512 * 512;
        int n = j >> 9, k = j & 511;
        g_wo16[j] = __float2half_rn(wo[(size_t)k * 512 + n]);
    }
}

// ================= Stage 1: fused bidirectional EMA (32 chunks x 18) =========
#define ESM_STATE (ECH * NDIM_ * 9)           // 4608 floats
#define ESM_Y     (ECL * ECH * 9)             // 5184 floats
#define ESM_TOTAL (2 * ESM_STATE + ESM_Y)     // 14400 floats = 57.6 KB

__global__ void __launch_bounds__(256, 2) ema_fused(const float* __restrict__ x,
                                                    const float* __restrict__ omega) {
    extern __shared__ float es[];
    float* Sf = es;
    float* Sb = es + ESM_STATE;
    float* Ys = es + 2 * ESM_STATE;

    int tid = threadIdx.x;
    int c = tid >> 3, dl = tid & 7;           // chunk, channel-lane
    int d = blockIdx.x * EDL + dl;
    int b = blockIdx.z;
    const float* xb = x + (size_t)b * N_ * DIM_ + d;
    __half*      yb = g_xm16 + (size_t)b * N_ * DIM_ + d;
    int t0 = c * ECL;

    if (tid < EDL) yb[0] = __float2half_rn(xb[0]);   // cls passthrough

    float q[NDIM_], q2[NDIM_], s[NDIM_];
#pragma unroll
    for (int n = 0; n < NDIM_; n++) { q[n] = g_cq[n][d]; s[n] = 0.f; }
#pragma unroll
    for (int tl = 0; tl < ECL; tl++) {
        float xv = xb[(size_t)(t0 + tl + 1) * DIM_];
#pragma unroll
        for (int n = 0; n < NDIM_; n++) s[n] = q[n] * s[n] + xv;
    }
#pragma unroll
    for (int n = 0; n < NDIM_; n++) Sf[(c * NDIM_ + n) * 9 + dl] = s[n];

#pragma unroll
    for (int n = 0; n < NDIM_; n++) { q2[n] = g_cq[n][d + DIM_]; s[n] = 0.f; }
#pragma unroll
    for (int tl = ECL - 1; tl >= 0; tl--) {
        float xv = xb[(size_t)(t0 + tl + 1) * DIM_];
#pragma unroll
        for (int n = 0; n < NDIM_; n++) s[n] = q2[n] * s[n] + xv;
    }
#pragma unroll
    for (int n = 0; n < NDIM_; n++) Sb[(c * NDIM_ + n) * 9 + dl] = s[n];
    __syncthreads();

    float cc[NDIM_];
#pragma unroll
    for (int n = 0; n < NDIM_; n++) {
        float qp = pow18f(q[n]);
        float Sin = 0.f;
        for (int cp = 0; cp < c; cp++)
            Sin = qp * Sin + Sf[(cp * NDIM_ + n) * 9 + dl];
        s[n] = Sin;
        cc[n] = g_cc[n][d];
    }
#pragma unroll
    for (int tl = 0; tl < ECL; tl++) {
        float xv = xb[(size_t)(t0 + tl + 1) * DIM_];
        float a[4] = {0.f, 0.f, 0.f, 0.f};
#pragma unroll
        for (int n = 0; n < NDIM_; n++) { s[n] = q[n] * s[n] + xv; a[n >> 2] += cc[n] * s[n]; }
        Ys[tl * (ECH * 9) + c * 9 + dl] = (a[0] + a[1]) + (a[2] + a[3]);
    }

#pragma unroll
    for (int n = 0; n < NDIM_; n++) {
        float qp = pow18f(q2[n]);
        float Sin = 0.f;
        for (int cp = ECH - 1; cp > c; cp--)
            Sin = qp * Sin + Sb[(cp * NDIM_ + n) * 9 + dl];
        s[n] = Sin;
        cc[n] = g_cc[n][d + DIM_];
    }
    float om = omega[d];
#pragma unroll
    for (int tl = ECL - 1; tl >= 0; tl--) {
        float xv = xb[(size_t)(t0 + tl + 1) * DIM_];
        float a[4] = {0.f, 0.f, 0.f, 0.f};
#pragma unroll
        for (int n = 0; n < NDIM_; n++) { s[n] = q2[n] * s[n] + xv; a[n >> 2] += cc[n] * s[n]; }
        float u = Ys[tl * (ECH * 9) + c * 9 + dl]
                + ((a[0] + a[1]) + (a[2] + a[3])) + xv * om;
        yb[(size_t)(t0 + tl + 1) * DIM_] = __float2half_rn(u / (1.f + __expf(-u)));
    }
}

// ======= fp16 GEMM (validated): 128x128 tile, 2-stage cp.async, persistent =====
#define AWSTR 20
#define TSLAB (128 * AWSTR)
#define GSMEM16_BYTES (4 * TSLAB * 4)

__device__ __forceinline__ void gemm16_tile(const __half* __restrict__ A,
                                            const __half* __restrict__ Bw, int M,
                                            __half* __restrict__ C16, int c16s,
                                            float* __restrict__ C32, int c32s,
                                            const float* __restrict__ bias, bool rnd,
                                            int bnb, int bmb) {
    extern __shared__ unsigned gsw[];
    unsigned* Asm = gsw;
    unsigned* Bsm = gsw + 2 * TSLAB;
    unsigned as_u = s2u(Asm), bs_u = s2u(Bsm);

    int tid = threadIdx.x, lane = tid & 31, w = tid >> 5;
    int gr = lane >> 2, tg = lane & 3;
    int wm = w & 1, wn = w >> 1;
    int bm = bmb * 128, bn = bnb * 128;

#define G16_ISSUE(s)                                                                   \
    do {                                                                               \
        int _buf = (s) & 1, _k0 = (s) * 32;                                            \
        unsigned _ad = as_u + (unsigned)(_buf * TSLAB * 4);                            \
        unsigned _bd = bs_u + (unsigned)(_buf * TSLAB * 4);                            \
        _Pragma("unroll")                                                              \
        for (int it = 0; it < 4; it++) {                                               \
            int idx = tid + it * 128;                                                  \
            int row = idx >> 2, cq = idx & 3;                                          \
            bool ok = (bm + row < M);                                                  \
            const __half* src = A + (size_t)(ok ? bm + row : 0) * 512 + _k0 + cq * 8;  \
            cp16(_ad + (unsigned)((row * AWSTR + cq * 4) * 4), src, ok ? 16 : 0);      \
        }                                                                              \
        _Pragma("unroll")                                                              \
        for (int it = 0; it < 4; it++) {                                               \
            int idx = tid + it * 128;                                                  \
            int row = idx >> 2, cq = idx & 3;                                          \
            cp16(_bd + (unsigned)((row * AWSTR + cq * 4) * 4),                         \
                 Bw + (size_t)(bn + row) * 512 + _k0 + cq * 8, 16);                    \
        }                                                                              \
    } while (0)

    G16_ISSUE(0); CP_COMMIT();

    float acc[4][8][4];
#pragma unroll
    for (int mt = 0; mt < 4; mt++)
#pragma unroll
        for (int nt = 0; nt < 8; nt++)
#pragma unroll
            for (int e = 0; e < 4; e++) acc[mt][nt][e] = 0.f;

    for (int s = 0; s < 16; s++) {
        __syncthreads();
        if (s + 1 < 16) G16_ISSUE(s + 1);
        CP_COMMIT();
        CP_WAIT1();
        __syncthreads();
        const unsigned* Ab = Asm + (s & 1) * TSLAB;
        const unsigned* Bb = Bsm + (s & 1) * TSLAB;
#pragma unroll
        for (int kk = 0; kk < 2; kk++) {
            unsigned a[4][4];
#pragma unroll
            for (int mt = 0; mt < 4; mt++) {
                int r = wm * 64 + mt * 16 + gr;
                int cw = kk * 8 + tg;
                a[mt][0] = Ab[r * AWSTR + cw];
                a[mt][1] = Ab[(r + 8) * AWSTR + cw];
                a[mt][2] = Ab[r * AWSTR + cw + 4];
                a[mt][3] = Ab[(r + 8) * AWSTR + cw + 4];
            }
            unsigned bf[8][2];
#pragma unroll
            for (int nt = 0; nt < 8; nt++) {
                int n = wn * 64 + nt * 8 + gr;
                bf[nt][0] = Bb[n * AWSTR + kk * 8 + tg];
                bf[nt][1] = Bb[n * AWSTR + kk * 8 + tg + 4];
            }
#pragma unroll
            for (int nt = 0; nt < 8; nt++)
#pragma unroll
                for (int mt = 0; mt < 4; mt++) mma16(acc[mt][nt], a[mt], bf[nt][0], bf[nt][1]);
        }
    }
#pragma unroll
    for (int mt = 0; mt < 4; mt++) {
        int r0 = bm + wm * 64 + mt * 16 + gr;
#pragma unroll
        for (int nt = 0; nt < 8; nt++) {
            int col = bn + wn * 64 + nt * 8 + 2 * tg;
            if (C16) {
                if (r0 < M)
                    *(unsigned*)(C16 + (size_t)r0 * c16s + col) =
                        pack2(acc[mt][nt][0], acc[mt][nt][1]);
                if (r0 + 8 < M)
                    *(unsigned*)(C16 + (size_t)(r0 + 8) * c16s + col) =
                        pack2(acc[mt][nt][2], acc[mt][nt][3]);
            } else {
                float bx = bias ? bias[col] : 0.f, by = bias ? bias[col + 1] : 0.f;
                float e0 = acc[mt][nt][0] + bx, e1 = acc[mt][nt][1] + by;
                float e2 = acc[mt][nt][2] + bx, e3 = acc[mt][nt][3] + by;
                if (rnd) { e0 = f2tff(e0); e1 = f2tff(e1); e2 = f2tff(e2); e3 = f2tff(e3); }
                if (r0 < M)     *(float2*)(C32 + (size_t)r0 * c32s + col)       = make_float2(e0, e1);
                if (r0 + 8 < M) *(float2*)(C32 + (size_t)(r0 + 8) * c32s + col) = make_float2(e2, e3);
            }
        }
    }
#undef G16_ISSUE
}

#define MB_ ((M_ROWS + 127) / 128)   // 145
#define GEMM_GRID 444

__global__ void __launch_bounds__(128, 3) gemm_qkv_tc() {
    for (int t = blockIdx.x; t < MB_ * 12; t += GEMM_GRID) {
        if (t < MB_ * 8)
            gemm16_tile(g_xm16, g_wqk16, M_ROWS, g_qk16, 1024, nullptr, 0, nullptr, false,
                        t & 7, t >> 3);
        else {
            int tt = t - MB_ * 8;
            gemm16_tile(g_xm16, g_wv16, M_ROWS, nullptr, 0, g_v, 512, nullptr, true,
                        tt & 3, tt >> 2);
        }
    }
}
__global__ void __launch_bounds__(128, 3) gemm_out_tc(const float* __restrict__ bias,
                                                      float* __restrict__ out) {
    for (int t = blockIdx.x; t < MB_ * 4; t += GEMM_GRID)
        gemm16_tile(g_ao16, g_wo16, M_ROWS, nullptr, 0, out, 512, bias, false, t & 3, t >> 2);
}

// ===== Stage 2b: V transpose  g_v fp32 -> g_vt16 fp16 [b][512][VTP] =====
__global__ void vt_kernel() {
    __shared__ float ts[32][33];
    int tx = threadIdx.x, ty = threadIdx.y;
    int n0 = blockIdx.x * 32, d0 = blockIdx.y * 32, b = blockIdx.z;
#pragma unroll
    for (int i = 0; i < 4; i++) {
        int n = n0 + ty + i * 8;
        ts[ty + i * 8][tx] = (n < N_) ? g_v[((size_t)b * N_ + n) * 512 + d0 + tx] : 0.f;
    }
    __syncthreads();
#pragma unroll
    for (int i = 0; i < 4; i++) {
        int d = d0 + ty + i * 8;
        g_vt16[((size_t)b * 512 + d) * VTP + n0 + tx] = __float2half_rn(ts[tx][ty + i * 8]);
    }
}

// ================= Stage 3: fp16 flash attention (round-14 verbatim) =================
#define FKSTR 36
#define FKBUF (64 * FKSTR)
#define QROWS 96
#define NT_ ((N_ + 63) / 64)
#define FSMEM_BYTES (4 * FKBUF * 4 + (2 * N_ - 1) * 4)

__global__ void __launch_bounds__(192, 2) flash_attn_tc(const float* __restrict__ rb) {
    extern __shared__ unsigned fsw[];
    unsigned* Ksw = fsw;
    unsigned* Vsw = fsw + 2 * FKBUF;
    float*    RBs = (float*)(fsw + 4 * FKBUF);
    unsigned ks_u = s2u(Ksw), vs_u = s2u(Vsw);

    int b = blockIdx.z, h = blockIdx.y;
    int i0 = blockIdx.x * QROWS;
    int tid = threadIdx.x, lane = tid & 31, w = tid >> 5;
    int gr = lane >> 2, tg = lane & 3;

    const __half* kb16 = g_qk16 + (size_t)b * N_ * 1024 + 512 + h * 64;
    const __half* vtb  = g_vt16 + ((size_t)b * 512 + h * 64) * VTP;
    const unsigned* qw = (const unsigned*)g_qk16 + (size_t)b * N_ * 512 + h * 32;

    for (int t = tid; t < 2 * N_ - 1; t += 192) RBs[t] = rb[t];

#define FL_ISSUE(jt)                                                                   \
    do {                                                                               \
        int _buf = (jt) & 1, _j0 = (jt) * 64;                                          \
        unsigned _kd = ks_u + (unsigned)(_buf * FKBUF * 4);                            \
        unsigned _vd = vs_u + (unsigned)(_buf * FKBUF * 4);                            \
        for (int idx = tid; idx < 512; idx += 192) {                                   \
            int j = idx >> 3, ch = idx & 7;                                            \
            bool ok = (_j0 + j < N_);                                                  \
            cp16(_kd + (unsigned)((j * FKSTR + ch * 4) * 4),                           \
                 kb16 + (size_t)(ok ? _j0 + j : 0) * 1024 + ch * 8, ok ? 16 : 0);      \
        }                                                                              \
        for (int idx = tid; idx < 512; idx += 192) {                                   \
            int dd = idx >> 3, ch = idx & 7;                                           \
            cp16(_vd + (unsigned)((dd * FKSTR + ch * 4) * 4),                          \
                 vtb + (size_t)dd * VTP + _j0 + ch * 8, 16);                           \
        }                                                                              \
    } while (0)

    unsigned qa[4][4];
    int rlo = i0 + w * 16 + gr;
    int rhi = rlo + 8;
#pragma unroll
    for (int kk = 0; kk < 4; kk++) {
        qa[kk][0] = (rlo < N_) ? qw[(size_t)rlo * 512 + kk * 8 + tg]     : 0u;
        qa[kk][1] = (rhi < N_) ? qw[(size_t)rhi * 512 + kk * 8 + tg]     : 0u;
        qa[kk][2] = (rlo < N_) ? qw[(size_t)rlo * 512 + kk * 8 + tg + 4] : 0u;
        qa[kk][3] = (rhi < N_) ? qw[(size_t)rhi * 512 + kk * 8 + tg + 4] : 0u;
    }

    FL_ISSUE(0); CP_COMMIT();

    float o[8][4], ob[8][4];
#pragma unroll
    for (int nt = 0; nt < 8; nt++)
#pragma unroll
        for (int e = 0; e < 4; e++) { o[nt][e] = 0.f; ob[nt][e] = 0.f; }
    float mlo = -1e30f, mhi = -1e30f, zlo = 0.f, zhi = 0.f;

    for (int jt = 0; jt < NT_; jt++) {
        int j0 = jt * 64;
        bool full = (j0 + 64 <= N_);
        __syncthreads();
        if (jt + 1 < NT_) FL_ISSUE(jt + 1);
        CP_COMMIT();
        CP_WAIT1();
        __syncthreads();
        const unsigned* Kb = Ksw + (jt & 1) * FKBUF;
        const unsigned* Vb = Vsw + (jt & 1) * FKBUF;

        float s[8][4];
#pragma unroll
        for (int nt = 0; nt < 8; nt++) {
#pragma unroll
            for (int e = 0; e < 4; e++) s[nt][e] = 0.f;
#pragma unroll
            for (int kk = 0; kk < 4; kk++) {
                unsigned b0 = Kb[(nt * 8 + gr) * FKSTR + kk * 8 + tg];
                unsigned b1 = Kb[(nt * 8 + gr) * FKSTR + kk * 8 + tg + 4];
                mma16(s[nt], qa[kk], b0, b1);
            }
#pragma unroll
            for (int e = 0; e < 4; e++) s[nt][e] *= 0.125f;
        }

        float tlo = -1e30f, thi = -1e30f;
#pragma unroll
        for (int nt = 0; nt < 8; nt++) {
            int col = j0 + nt * 8 + 2 * tg;
            if (full || col < N_)     { tlo = fmaxf(tlo, s[nt][0]); thi = fmaxf(thi, s[nt][2]); }
            if (full || col + 1 < N_) { tlo = fmaxf(tlo, s[nt][1]); thi = fmaxf(thi, s[nt][3]); }
        }
#pragma unroll
        for (int off = 1; off <= 2; off <<= 1) {
            tlo = fmaxf(tlo, __shfl_xor_sync(0xffffffffu, tlo, off));
            thi = fmaxf(thi, __shfl_xor_sync(0xffffffffu, thi, off));
        }
        float mlon = fmaxf(mlo, tlo), mhin = fmaxf(mhi, thi);
        float sclo = __expf(mlo - mlon), schi = __expf(mhi - mhin);
        float psl = 0.f, psh = 0.f;
        unsigned pp[8][2];
#pragma unroll
        for (int nt = 0; nt < 8; nt++) {
            int col = j0 + nt * 8 + 2 * tg;
            float p0 = (full || col     < N_) ? __expf(s[nt][0] - mlon) : 0.f;
            float p1 = (full || col + 1 < N_) ? __expf(s[nt][1] - mlon) : 0.f;
            float p2 = (full || col     < N_) ? __expf(s[nt][2] - mhin) : 0.f;
            float p3 = (full || col + 1 < N_) ? __expf(s[nt][3] - mhin) : 0.f;
            psl += p0 + p1; psh += p2 + p3;
            o[nt][0] *= sclo; o[nt][1] *= sclo;
            o[nt][2] *= schi; o[nt][3] *= schi;
            pp[nt][0] = pack2(p0, p1);
            pp[nt][1] = pack2(p2, p3);
        }
#pragma unroll
        for (int off = 1; off <= 2; off <<= 1) {
            psl += __shfl_xor_sync(0xffffffffu, psl, off);
            psh += __shfl_xor_sync(0xffffffffu, psh, off);
        }
        zlo = zlo * sclo + psl;  zhi = zhi * schi + psh;
        mlo = mlon;  mhi = mhin;

#pragma unroll
        for (int kk = 0; kk < 4; kk++) {
            unsigned pa[4] = { pp[2 * kk][0], pp[2 * kk][1],
                               pp[2 * kk + 1][0], pp[2 * kk + 1][1] };
            unsigned ba[4];
            int jb = j0 + kk * 16 + 2 * tg;
            float b00 = (rlo < N_ && jb     < N_) ? RBs[576 + jb - rlo]     : 0.f;
            float b01 = (rlo < N_ && jb + 1 < N_) ? RBs[576 + jb + 1 - rlo] : 0.f;
            float b10 = (rhi < N_ && jb     < N_) ? RBs[576 + jb - rhi]     : 0.f;
            float b11 = (rhi < N_ && jb + 1 < N_) ? RBs[576 + jb + 1 - rhi] : 0.f;
            float b20 = (rlo < N_ && jb + 8 < N_) ? RBs[576 + jb + 8 - rlo] : 0.f;
            float b21 = (rlo < N_ && jb + 9 < N_) ? RBs[576 + jb + 9 - rlo] : 0.f;
            float b30 = (rhi < N_ && jb + 8 < N_) ? RBs[576 + jb + 8 - rhi] : 0.f;
            float b31 = (rhi < N_ && jb + 9 < N_) ? RBs[576 + jb + 9 - rhi] : 0.f;
            ba[0] = pack2(b00, b01); ba[1] = pack2(b10, b11);
            ba[2] = pack2(b20, b21); ba[3] = pack2(b30, b31);
#pragma unroll
            for (int nt = 0; nt < 8; nt++) {
                unsigned v0 = Vb[(nt * 8 + gr) * FKSTR + kk * 8 + tg];
                unsigned v1 = Vb[(nt * 8 + gr) * FKSTR + kk * 8 + tg + 4];
                mma16(o[nt],  pa, v0, v1);
                mma16(ob[nt], ba, v0, v1);
            }
        }
    }

    float izlo = 1.f / zlo, izhi = 1.f / zhi;
#pragma unroll
    for (int nt = 0; nt < 8; nt++) {
        int col = h * 64 + nt * 8 + 2 * tg;
        if (rlo < N_)
            *(unsigned*)(g_ao16 + ((size_t)b * N_ + rlo) * 512 + col) =
                pack2(o[nt][0] * izlo + ob[nt][0], o[nt][1] * izlo + ob[nt][1]);
        if (rhi < N_)
            *(unsigned*)(g_ao16 + ((size_t)b * N_ + rhi) * 512 + col) =
                pack2(o[nt][2] * izhi + ob[nt][2], o[nt][3] * izhi + ob[nt][3]);
    }
#undef FL_ISSUE
}

// ================= launch =================
extern "C" void kernel_launch(void* const* d_in, const int* in_sizes, int n_in,
                              void* d_out, int out_size) {
    const float* x         = (const float*)d_in[0];
    const float* W_qk      = (const float*)d_in[1];
    const float* W_v       = (const float*)d_in[2];
    const float* W_out     = (const float*)d_in[3];
    const float* b_out     = (const float*)d_in[4];
    const float* rel_bias  = (const float*)d_in[5];
    const float* ema_delta = (const float*)d_in[6];
    const float* ema_alpha = (const float*)d_in[7];
    const float* ema_beta  = (const float*)d_in[8];
    const float* ema_gamma = (const float*)d_in[9];
    const float* ema_omega = (const float*)d_in[10];
    float* out = (float*)d_out;

    static int attr_set = 0;
    if (!attr_set) {
        cudaFuncSetAttribute(ema_fused, cudaFuncAttributeMaxDynamicSharedMemorySize,
                             ESM_TOTAL * (int)sizeof(float));
        cudaFuncSetAttribute(gemm_qkv_tc, cudaFuncAttributeMaxDynamicSharedMemorySize, GSMEM16_BYTES);
        cudaFuncSetAttribute(gemm_out_tc, cudaFuncAttributeMaxDynamicSharedMemorySize, GSMEM16_BYTES);
        cudaFuncSetAttribute(flash_attn_tc, cudaFuncAttributeMaxDynamicSharedMemorySize, FSMEM_BYTES);
        attr_set = 1;
    }

    coef_kernel<<<(2 * DIM_ * NDIM_ + 255) / 256, 256>>>(ema_delta, ema_alpha, ema_beta, ema_gamma);
    tcvt_all<<<(1024 * 512 + 2 * 512 * 512 + 255) / 256, 256>>>(W_qk, W_v, W_out);
    ema_fused<<<dim3(DIM_ / EDL, 1, B_), 256, ESM_TOTAL * sizeof(float)>>>(x, ema_omega);

    gemm_qkv_tc<<<GEMM_GRID, 128, GSMEM16_BYTES>>>();
    vt_kernel<<<dim3(VTP / 32, 16, B_), dim3(32, 8)>>>();

    flash_attn_tc<<<dim3((N_ + QROWS - 1) / QROWS, HEADS_, B_), 192, FSMEM_BYTES>>>(rel_bias);

    gemm_out_tc<<<GEMM_GRID, 128, GSMEM16_BYTES>>>(b_out, out);
}

// round 16
// speedup vs baseline: 1.0166x; 1.0166x over previous
#include <cuda_runtime.h>
#include <cuda_fp16.h>

#define B_     32
#define N_     577
#define L_     576
#define DIM_   512
#define HEADS_ 8
#define NDIM_  16
#define M_ROWS (B_ * N_)   // 18464
#define ECH 16             // EMA chunks (round-14 validated config)
#define ECL 36
#define VTP 640            // padded j-extent of V^T

// -------- scratch (device globals; __half arrays 16B-aligned for cp.async) --------
// RULE: NEVER pass these as host-side kernel arguments (host shadow symbol!).
__device__ __align__(16) __half g_xm16[(size_t)B_ * N_ * DIM_];
__device__ __align__(16) __half g_qk16[(size_t)B_ * N_ * 1024];
__device__ float g_v [(size_t)B_ * N_ * 512];
__device__ __align__(16) __half g_vt16[(size_t)B_ * 512 * VTP];
__device__ __align__(16) __half g_ao16[(size_t)B_ * N_ * 512];
__device__ float g_cq[NDIM_][2 * DIM_];
__device__ float g_cc[NDIM_][2 * DIM_];
__device__ __align__(16) __half g_wqk16[1024 * 512];
__device__ __align__(16) __half g_wv16 [512 * 512];
__device__ __align__(16) __half g_wo16 [512 * 512];

// ---------------- helpers ----------------
__device__ __forceinline__ unsigned f2tf(float x) {
    unsigned u;
    asm("cvt.rna.tf32.f32 %0, %1;" : "=r"(u) : "f"(x));
    return u;
}
__device__ __forceinline__ float f2tff(float x) { return __uint_as_float(f2tf(x)); }
__device__ __forceinline__ unsigned pack2(float x, float y) {
    __half2 h = __floats2half2_rn(x, y);
    return *reinterpret_cast<unsigned*>(&h);
}
__device__ __forceinline__ void mma16(float* c, const unsigned* a, unsigned b0, unsigned b1) {
    asm volatile(
        "mma.sync.aligned.m16n8k16.row.col.f32.f16.f16.f32 "
        "{%0,%1,%2,%3},{%4,%5,%6,%7},{%8,%9},{%0,%1,%2,%3};"
        : "+f"(c[0]), "+f"(c[1]), "+f"(c[2]), "+f"(c[3])
        : "r"(a[0]), "r"(a[1]), "r"(a[2]), "r"(a[3]), "r"(b0), "r"(b1));
}
__device__ __forceinline__ unsigned s2u(const void* p) {
    return (unsigned)__cvta_generic_to_shared(p);
}
__device__ __forceinline__ void cp16(unsigned dst, const void* src, int srcsz) {
    asm volatile("cp.async.cg.shared.global [%0], [%1], 16, %2;"
                 :: "r"(dst), "l"(src), "r"(srcsz));
}
#define CP_COMMIT() asm volatile("cp.async.commit_group;")
#define CP_WAIT1()  asm volatile("cp.async.wait_group 1;")
#define CP_WAIT2()  asm volatile("cp.async.wait_group 2;")

__device__ __forceinline__ float pow36f(float q) {
    float q2 = q * q, q4 = q2 * q2, q8 = q4 * q4, q16 = q8 * q8, q32 = q16 * q16;
    return q32 * q4;
}

// ================= Stage 0: EMA coefficients + fused weight prep =================
__global__ void coef_kernel(const float* __restrict__ delta, const float* __restrict__ alpha,
                            const float* __restrict__ beta,  const float* __restrict__ gamma) {
    int idx = blockIdx.x * blockDim.x + threadIdx.x;
    if (idx >= 2 * DIM_ * NDIM_) return;
    int d = idx / NDIM_;
    int n = idx % NDIM_;
    float p  = 1.f / (1.f + expf(-delta[idx]));
    float sa = 1.f / (1.f + expf(-alpha[idx]));
    g_cq[n][d] = 1.f - p * sa;
    g_cc[n][d] = p * beta[idx] * gamma[idx] * 0.25f;
}

__global__ void tcvt_all(const float* __restrict__ wqk, const float* __restrict__ wv,
                         const float* __restrict__ wo) {
    int i = blockIdx.x * 256 + threadIdx.x;
    if (i < 1024 * 512) {
        int n = i >> 9, k = i & 511;
        g_wqk16[i] = __float2half_rn(wqk[(size_t)k * 1024 + n]);
    } else if (i < 1024 * 512 + 512 * 512) {
        int j = i - 1024 * 512;
        int n = j >> 9, k = j & 511;
        g_wv16[j] = __float2half_rn(wv[(size_t)k * 512 + n]);
    } else if (i < 1024 * 512 + 2 * 512 * 512) {
        int j = i - 1024 * 512 - 512 * 512;
        int n = j >> 9, k = j & 511;
        g_wo16[j] = __float2half_rn(wo[(size_t)k * 512 + n]);
    }
}

// ================= Stage 1: fused bidirectional EMA (round-14 validated) =========
#define ESM_STATE (ECH * NDIM_ * 17)
#define ESM_Y     (ECL * ECH * 17)
#define ESM_TOTAL (2 * ESM_STATE + ESM_Y)

__global__ void __launch_bounds__(256, 2) ema_fused(const float* __restrict__ x,
                                                    const float* __restrict__ omega) {
    extern __shared__ float es[];
    float* Sf = es;
    float* Sb = es + ESM_STATE;
    float* Ys = es + 2 * ESM_STATE;

    int tid = threadIdx.x;
    int c = tid >> 4, dl = tid & 15;
    int d = blockIdx.x * 16 + dl;
    int b = blockIdx.z;
    const float* xb = x + (size_t)b * N_ * DIM_ + d;
    __half*      yb = g_xm16 + (size_t)b * N_ * DIM_ + d;
    int t0 = c * ECL;

    if (tid < 16) yb[0] = __float2half_rn(xb[0]);

    float q[NDIM_], q2[NDIM_], s[NDIM_];
#pragma unroll
    for (int n = 0; n < NDIM_; n++) { q[n] = g_cq[n][d]; s[n] = 0.f; }
#pragma unroll 4
    for (int tl = 0; tl < ECL; tl++) {
        float xv = xb[(size_t)(t0 + tl + 1) * DIM_];
#pragma unroll
        for (int n = 0; n < NDIM_; n++) s[n] = q[n] * s[n] + xv;
    }
#pragma unroll
    for (int n = 0; n < NDIM_; n++) Sf[(c * NDIM_ + n) * 17 + dl] = s[n];

#pragma unroll
    for (int n = 0; n < NDIM_; n++) { q2[n] = g_cq[n][d + DIM_]; s[n] = 0.f; }
#pragma unroll 4
    for (int tl = ECL - 1; tl >= 0; tl--) {
        float xv = xb[(size_t)(t0 + tl + 1) * DIM_];
#pragma unroll
        for (int n = 0; n < NDIM_; n++) s[n] = q2[n] * s[n] + xv;
    }
#pragma unroll
    for (int n = 0; n < NDIM_; n++) Sb[(c * NDIM_ + n) * 17 + dl] = s[n];
    __syncthreads();

    float cc[NDIM_];
#pragma unroll
    for (int n = 0; n < NDIM_; n++) {
        float qp = pow36f(q[n]);
        float Sin = 0.f;
        for (int cp = 0; cp < c; cp++)
            Sin = qp * Sin + Sf[(cp * NDIM_ + n) * 17 + dl];
        s[n] = Sin;
        cc[n] = g_cc[n][d];
    }
#pragma unroll 4
    for (int tl = 0; tl < ECL; tl++) {
        float xv = xb[(size_t)(t0 + tl + 1) * DIM_];
        float a[4] = {0.f, 0.f, 0.f, 0.f};
#pragma unroll
        for (int n = 0; n < NDIM_; n++) { s[n] = q[n] * s[n] + xv; a[n >> 2] += cc[n] * s[n]; }
        Ys[tl * (ECH * 17) + c * 17 + dl] = (a[0] + a[1]) + (a[2] + a[3]);
    }

#pragma unroll
    for (int n = 0; n < NDIM_; n++) {
        float qp = pow36f(q2[n]);
        float Sin = 0.f;
        for (int cp = ECH - 1; cp > c; cp--)
            Sin = qp * Sin + Sb[(cp * NDIM_ + n) * 17 + dl];
        s[n] = Sin;
        cc[n] = g_cc[n][d + DIM_];
    }
    float om = omega[d];
#pragma unroll 4
    for (int tl = ECL - 1; tl >= 0; tl--) {
        float xv = xb[(size_t)(t0 + tl + 1) * DIM_];
        float a[4] = {0.f, 0.f, 0.f, 0.f};
#pragma unroll
        for (int n = 0; n < NDIM_; n++) { s[n] = q2[n] * s[n] + xv; a[n >> 2] += cc[n] * s[n]; }
        float u = Ys[tl * (ECH * 17) + c * 17 + dl]
                + ((a[0] + a[1]) + (a[2] + a[3])) + xv * om;
        yb[(size_t)(t0 + tl + 1) * DIM_] = __float2half_rn(u / (1.f + __expf(-u)));
    }
}

// ======= fp16 GEMM: 128x128 tile, 3-stage cp.async, persistent =====
#define AWSTR 20
#define TSLAB (128 * AWSTR)
#define GSMEM16_BYTES (6 * TSLAB * 4)   // 61440 B -> 3 CTAs/SM

__device__ __forceinline__ void gemm16_tile(const __half* __restrict__ A,
                                            const __half* __restrict__ Bw, int M,
                                            __half* __restrict__ C16, int c16s,
                                            float* __restrict__ C32, int c32s,
                                            const float* __restrict__ bias, bool rnd,
                                            int bnb, int bmb) {
    extern __shared__ unsigned gsw[];
    unsigned* Asm = gsw;                 // [3][TSLAB]
    unsigned* Bsm = gsw + 3 * TSLAB;     // [3][TSLAB]
    unsigned as_u = s2u(Asm), bs_u = s2u(Bsm);

    int tid = threadIdx.x, lane = tid & 31, w = tid >> 5;
    int gr = lane >> 2, tg = lane & 3;
    int wm = w & 1, wn = w >> 1;
    int bm = bmb * 128, bn = bnb * 128;

#define G16_ISSUE(s)                                                                   \
    do {                                                                               \
        int _buf = (s) % 3, _k0 = (s) * 32;                                            \
        unsigned _ad = as_u + (unsigned)(_buf * TSLAB * 4);                            \
        unsigned _bd = bs_u + (unsigned)(_buf * TSLAB * 4);                            \
        _Pragma("unroll")                                                              \
        for (int it = 0; it < 4; it++) {                                               \
            int idx = tid + it * 128;                                                  \
            int row = idx >> 2, cq = idx & 3;                                          \
            bool ok = (bm + row < M);                                                  \
            const __half* src = A + (size_t)(ok ? bm + row : 0) * 512 + _k0 + cq * 8;  \
            cp16(_ad + (unsigned)((row * AWSTR + cq * 4) * 4), src, ok ? 16 : 0);      \
        }                                                                              \
        _Pragma("unroll")                                                              \
        for (int it = 0; it < 4; it++) {                                               \
            int idx = tid + it * 128;                                                  \
            int row = idx >> 2, cq = idx & 3;                                          \
            cp16(_bd + (unsigned)((row * AWSTR + cq * 4) * 4),                         \
                 Bw + (size_t)(bn + row) * 512 + _k0 + cq * 8, 16);                    \
        }                                                                              \
    } while (0)

    G16_ISSUE(0); CP_COMMIT();
    G16_ISSUE(1); CP_COMMIT();

    float acc[4][8][4];
#pragma unroll
    for (int mt = 0; mt < 4; mt++)
#pragma unroll
        for (int nt = 0; nt < 8; nt++)
#pragma unroll
            for (int e = 0; e < 4; e++) acc[mt][nt][e] = 0.f;

    for (int s = 0; s < 16; s++) {
        if (s + 2 < 16) G16_ISSUE(s + 2);
        CP_COMMIT();                     // always commit: group count stays exact
        CP_WAIT2();                      // slab s landed (2 newer groups pending)
        __syncthreads();
        const unsigned* Ab = Asm + (s % 3) * TSLAB;
        const unsigned* Bb = Bsm + (s % 3) * TSLAB;
#pragma unroll
        for (int kk = 0; kk < 2; kk++) {
            unsigned a[4][4];
#pragma unroll
            for (int mt = 0; mt < 4; mt++) {
                int r = wm * 64 + mt * 16 + gr;
                int cw = kk * 8 + tg;
                a[mt][0] = Ab[r * AWSTR + cw];
                a[mt][1] = Ab[(r + 8) * AWSTR + cw];
                a[mt][2] = Ab[r * AWSTR + cw + 4];
                a[mt][3] = Ab[(r + 8) * AWSTR + cw + 4];
            }
            unsigned bf[8][2];
#pragma unroll
            for (int nt = 0; nt < 8; nt++) {
                int n = wn * 64 + nt * 8 + gr;
                bf[nt][0] = Bb[n * AWSTR + kk * 8 + tg];
                bf[nt][1] = Bb[n * AWSTR + kk * 8 + tg + 4];
            }
#pragma unroll
            for (int nt = 0; nt < 8; nt++)
#pragma unroll
                for (int mt = 0; mt < 4; mt++) mma16(acc[mt][nt], a[mt], bf[nt][0], bf[nt][1]);
        }
        __syncthreads();                 // buffer s%3 free before iter s+1 issues s+3
    }
#pragma unroll
    for (int mt = 0; mt < 4; mt++) {
        int r0 = bm + wm * 64 + mt * 16 + gr;
#pragma unroll
        for (int nt = 0; nt < 8; nt++) {
            int col = bn + wn * 64 + nt * 8 + 2 * tg;
            if (C16) {
                if (r0 < M)
                    *(unsigned*)(C16 + (size_t)r0 * c16s + col) =
                        pack2(acc[mt][nt][0], acc[mt][nt][1]);
                if (r0 + 8 < M)
                    *(unsigned*)(C16 + (size_t)(r0 + 8) * c16s + col) =
                        pack2(acc[mt][nt][2], acc[mt][nt][3]);
            } else {
                float bx = bias ? bias[col] : 0.f, by = bias ? bias[col + 1] : 0.f;
                float e0 = acc[mt][nt][0] + bx, e1 = acc[mt][nt][1] + by;
                float e2 = acc[mt][nt][2] + bx, e3 = acc[mt][nt][3] + by;
                if (rnd) { e0 = f2tff(e0); e1 = f2tff(e1); e2 = f2tff(e2); e3 = f2tff(e3); }
                if (r0 < M)     *(float2*)(C32 + (size_t)r0 * c32s + col)       = make_float2(e0, e1);
                if (r0 + 8 < M) *(float2*)(C32 + (size_t)(r0 + 8) * c32s + col) = make_float2(e2, e3);
            }
        }
    }
#undef G16_ISSUE
}

#define MB_ ((M_ROWS + 127) / 128)   // 145
#define GEMM_GRID 444

__global__ void __launch_bounds__(128, 3) gemm_qkv_tc() {
    for (int t = blockIdx.x; t < MB_ * 12; t += GEMM_GRID) {
        if (t < MB_ * 8)
            gemm16_tile(g_xm16, g_wqk16, M_ROWS, g_qk16, 1024, nullptr, 0, nullptr, false,
                        t & 7, t >> 3);
        else {
            int tt = t - MB_ * 8;
            gemm16_tile(g_xm16, g_wv16, M_ROWS, nullptr, 0, g_v, 512, nullptr, true,
                        tt & 3, tt >> 2);
        }
    }
}
__global__ void __launch_bounds__(128, 3) gemm_out_tc(const float* __restrict__ bias,
                                                      float* __restrict__ out) {
    for (int t = blockIdx.x; t < MB_ * 4; t += GEMM_GRID)
        gemm16_tile(g_ao16, g_wo16, M_ROWS, nullptr, 0, out, 512, bias, false, t & 3, t >> 2);
}

// ===== Stage 2b: V transpose  g_v fp32 -> g_vt16 fp16 [b][512][VTP] =====
__global__ void vt_kernel() {
    __shared__ float ts[32][33];
    int tx = threadIdx.x, ty = threadIdx.y;
    int n0 = blockIdx.x * 32, d0 = blockIdx.y * 32, b = blockIdx.z;
#pragma unroll
    for (int i = 0; i < 4; i++) {
        int n = n0 + ty + i * 8;
        ts[ty + i * 8][tx] = (n < N_) ? g_v[((size_t)b * N_ + n) * 512 + d0 + tx] : 0.f;
    }
    __syncthreads();
#pragma unroll
    for (int i = 0; i < 4; i++) {
        int d = d0 + ty + i * 8;
        g_vt16[((size_t)b * 512 + d) * VTP + n0 + tx] = __float2half_rn(ts[tx][ty + i * 8]);
    }
}

// ================= Stage 3: fp16 flash attention (round-14 verbatim) =================
#define FKSTR 36
#define FKBUF (64 * FKSTR)
#define QROWS 96
#define NT_ ((N_ + 63) / 64)
#define FSMEM_BYTES (4 * FKBUF * 4 + (2 * N_ - 1) * 4)

__global__ void __launch_bounds__(192, 2) flash_attn_tc(const float* __restrict__ rb) {
    extern __shared__ unsigned fsw[];
    unsigned* Ksw = fsw;
    unsigned* Vsw = fsw + 2 * FKBUF;
    float*    RBs = (float*)(fsw + 4 * FKBUF);
    unsigned ks_u = s2u(Ksw), vs_u = s2u(Vsw);

    int b = blockIdx.z, h = blockIdx.y;
    int i0 = blockIdx.x * QROWS;
    int tid = threadIdx.x, lane = tid & 31, w = tid >> 5;
    int gr = lane >> 2, tg = lane & 3;

    const __half* kb16 = g_qk16 + (size_t)b * N_ * 1024 + 512 + h * 64;
    const __half* vtb  = g_vt16 + ((size_t)b * 512 + h * 64) * VTP;
    const unsigned* qw = (const unsigned*)g_qk16 + (size_t)b * N_ * 512 + h * 32;

    for (int t = tid; t < 2 * N_ - 1; t += 192) RBs[t] = rb[t];

#define FL_ISSUE(jt)                                                                   \
    do {                                                                               \
        int _buf = (jt) & 1, _j0 = (jt) * 64;                                          \
        unsigned _kd = ks_u + (unsigned)(_buf * FKBUF * 4);                            \
        unsigned _vd = vs_u + (unsigned)(_buf * FKBUF * 4);                            \
        for (int idx = tid; idx < 512; idx += 192) {                                   \
            int j = idx >> 3, ch = idx & 7;                                            \
            bool ok = (_j0 + j < N_);                                                  \
            cp16(_kd + (unsigned)((j * FKSTR + ch * 4) * 4),                           \
                 kb16 + (size_t)(ok ? _j0 + j : 0) * 1024 + ch * 8, ok ? 16 : 0);      \
        }                                                                              \
        for (int idx = tid; idx < 512; idx += 192) {                                   \
            int dd = idx >> 3, ch = idx & 7;                                           \
            cp16(_vd + (unsigned)((dd * FKSTR + ch * 4) * 4),                          \
                 vtb + (size_t)dd * VTP + _j0 + ch * 8, 16);                           \
        }                                                                              \
    } while (0)

    unsigned qa[4][4];
    int rlo = i0 + w * 16 + gr;
    int rhi = rlo + 8;
#pragma unroll
    for (int kk = 0; kk < 4; kk++) {
        qa[kk][0] = (rlo < N_) ? qw[(size_t)rlo * 512 + kk * 8 + tg]     : 0u;
        qa[kk][1] = (rhi < N_) ? qw[(size_t)rhi * 512 + kk * 8 + tg]     : 0u;
        qa[kk][2] = (rlo < N_) ? qw[(size_t)rlo * 512 + kk * 8 + tg + 4] : 0u;
        qa[kk][3] = (rhi < N_) ? qw[(size_t)rhi * 512 + kk * 8 + tg + 4] : 0u;
    }

    FL_ISSUE(0); CP_COMMIT();

    float o[8][4], ob[8][4];
#pragma unroll
    for (int nt = 0; nt < 8; nt++)
#pragma unroll
        for (int e = 0; e < 4; e++) { o[nt][e] = 0.f; ob[nt][e] = 0.f; }
    float mlo = -1e30f, mhi = -1e30f, zlo = 0.f, zhi = 0.f;

    for (int jt = 0; jt < NT_; jt++) {
        int j0 = jt * 64;
        bool full = (j0 + 64 <= N_);
        __syncthreads();
        if (jt + 1 < NT_) FL_ISSUE(jt + 1);
        CP_COMMIT();
        CP_WAIT1();
        __syncthreads();
        const unsigned* Kb = Ksw + (jt & 1) * FKBUF;
        const unsigned* Vb = Vsw + (jt & 1) * FKBUF;

        float s[8][4];
#pragma unroll
        for (int nt = 0; nt < 8; nt++) {
#pragma unroll
            for (int e = 0; e < 4; e++) s[nt][e] = 0.f;
#pragma unroll
            for (int kk = 0; kk < 4; kk++) {
                unsigned b0 = Kb[(nt * 8 + gr) * FKSTR + kk * 8 + tg];
                unsigned b1 = Kb[(nt * 8 + gr) * FKSTR + kk * 8 + tg + 4];
                mma16(s[nt], qa[kk], b0, b1);
            }
#pragma unroll
            for (int e = 0; e < 4; e++) s[nt][e] *= 0.125f;
        }

        float tlo = -1e30f, thi = -1e30f;
#pragma unroll
        for (int nt = 0; nt < 8; nt++) {
            int col = j0 + nt * 8 + 2 * tg;
            if (full || col < N_)     { tlo = fmaxf(tlo, s[nt][0]); thi = fmaxf(thi, s[nt][2]); }
            if (full || col + 1 < N_) { tlo = fmaxf(tlo, s[nt][1]); thi = fmaxf(thi, s[nt][3]); }
        }
#pragma unroll
        for (int off = 1; off <= 2; off <<= 1) {
            tlo = fmaxf(tlo, __shfl_xor_sync(0xffffffffu, tlo, off));
            thi = fmaxf(thi, __shfl_xor_sync(0xffffffffu, thi, off));
        }
        float mlon = fmaxf(mlo, tlo), mhin = fmaxf(mhi, thi);
        float sclo = __expf(mlo - mlon), schi = __expf(mhi - mhin);
        float psl = 0.f, psh = 0.f;
        unsigned pp[8][2];
#pragma unroll
        for (int nt = 0; nt < 8; nt++) {
            int col = j0 + nt * 8 + 2 * tg;
            float p0 = (full || col     < N_) ? __expf(s[nt][0] - mlon) : 0.f;
            float p1 = (full || col + 1 < N_) ? __expf(s[nt][1] - mlon) : 0.f;
            float p2 = (full || col     < N_) ? __expf(s[nt][2] - mhin) : 0.f;
            float p3 = (full || col + 1 < N_) ? __expf(s[nt][3] - mhin) : 0.f;
            psl += p0 + p1; psh += p2 + p3;
            o[nt][0] *= sclo; o[nt][1] *= sclo;
            o[nt][2] *= schi; o[nt][3] *= schi;
            pp[nt][0] = pack2(p0, p1);
            pp[nt][1] = pack2(p2, p3);
        }
#pragma unroll
        for (int off = 1; off <= 2; off <<= 1) {
            psl += __shfl_xor_sync(0xffffffffu, psl, off);
            psh += __shfl_xor_sync(0xffffffffu, psh, off);
        }
        zlo = zlo * sclo + psl;  zhi = zhi * schi + psh;
        mlo = mlon;  mhi = mhin;

#pragma unroll
        for (int kk = 0; kk < 4; kk++) {
            unsigned pa[4] = { pp[2 * kk][0], pp[2 * kk][1],
                               pp[2 * kk + 1][0], pp[2 * kk + 1][1] };
            unsigned ba[4];
            int jb = j0 + kk * 16 + 2 * tg;
            float b00 = (rlo < N_ && jb     < N_) ? RBs[576 + jb - rlo]     : 0.f;
            float b01 = (rlo < N_ && jb + 1 < N_) ? RBs[576 + jb + 1 - rlo] : 0.f;
            float b10 = (rhi < N_ && jb     < N_) ? RBs[576 + jb - rhi]     : 0.f;
            float b11 = (rhi < N_ && jb + 1 < N_) ? RBs[576 + jb + 1 - rhi] : 0.f;
            float b20 = (rlo < N_ && jb + 8 < N_) ? RBs[576 + jb + 8 - rlo] : 0.f;
            float b21 = (rlo < N_ && jb + 9 < N_) ? RBs[576 + jb + 9 - rlo] : 0.f;
            float b30 = (rhi < N_ && jb + 8 < N_) ? RBs[576 + jb + 8 - rhi] : 0.f;
            float b31 = (rhi < N_ && jb + 9 < N_) ? RBs[576 + jb + 9 - rhi] : 0.f;
            ba[0] = pack2(b00, b01); ba[1] = pack2(b10, b11);
            ba[2] = pack2(b20, b21); ba[3] = pack2(b30, b31);
#pragma unroll
            for (int nt = 0; nt < 8; nt++) {
                unsigned v0 = Vb[(nt * 8 + gr) * FKSTR + kk * 8 + tg];
                unsigned v1 = Vb[(nt * 8 + gr) * FKSTR + kk * 8 + tg + 4];
                mma16(o[nt],  pa, v0, v1);
                mma16(ob[nt], ba, v0, v1);
            }
        }
    }

    float izlo = 1.f / zlo, izhi = 1.f / zhi;
#pragma unroll
    for (int nt = 0; nt < 8; nt++) {
        int col = h * 64 + nt * 8 + 2 * tg;
        if (rlo < N_)
            *(unsigned*)(g_ao16 + ((size_t)b * N_ + rlo) * 512 + col) =
                pack2(o[nt][0] * izlo + ob[nt][0], o[nt][1] * izlo + ob[nt][1]);
        if (rhi < N_)
            *(unsigned*)(g_ao16 + ((size_t)b * N_ + rhi) * 512 + col) =
                pack2(o[nt][2] * izhi + ob[nt][2], o[nt][3] * izhi + ob[nt][3]);
    }
#undef FL_ISSUE
}

// ================= launch =================
extern "C" void kernel_launch(void* const* d_in, const int* in_sizes, int n_in,
                              void* d_out, int out_size) {
    const float* x         = (const float*)d_in[0];
    const float* W_qk      = (const float*)d_in[1];
    const float* W_v       = (const float*)d_in[2];
    const float* W_out     = (const float*)d_in[3];
    const float* b_out     = (const float*)d_in[4];
    const float* rel_bias  = (const float*)d_in[5];
    const float* ema_delta = (const float*)d_in[6];
    const float* ema_alpha = (const float*)d_in[7];
    const float* ema_beta  = (const float*)d_in[8];
    const float* ema_gamma = (const float*)d_in[9];
    const float* ema_omega = (const float*)d_in[10];
    float* out = (float*)d_out;

    static int attr_set = 0;
    if (!attr_set) {
        cudaFuncSetAttribute(ema_fused, cudaFuncAttributeMaxDynamicSharedMemorySize,
                             ESM_TOTAL * (int)sizeof(float));
        cudaFuncSetAttribute(gemm_qkv_tc, cudaFuncAttributeMaxDynamicSharedMemorySize, GSMEM16_BYTES);
        cudaFuncSetAttribute(gemm_out_tc, cudaFuncAttributeMaxDynamicSharedMemorySize, GSMEM16_BYTES);
        cudaFuncSetAttribute(flash_attn_tc, cudaFuncAttributeMaxDynamicSharedMemorySize, FSMEM_BYTES);
        attr_set = 1;
    }

    coef_kernel<<<(2 * DIM_ * NDIM_ + 255) / 256, 256>>>(ema_delta, ema_alpha, ema_beta, ema_gamma);
    tcvt_all<<<(1024 * 512 + 2 * 512 * 512 + 255) / 256, 256>>>(W_qk, W_v, W_out);
    ema_fused<<<dim3(DIM_ / 16, 1, B_), 256, ESM_TOTAL * sizeof(float)>>>(x, ema_omega);

    gemm_qkv_tc<<<GEMM_GRID, 128, GSMEM16_BYTES>>>();
    vt_kernel<<<dim3(VTP / 32, 16, B_), dim3(32, 8)>>>();

    flash_attn_tc<<<dim3((N_ + QROWS - 1) / QROWS, HEADS_, B_), 192, FSMEM_BYTES>>>(rel_bias);

    gemm_out_tc<<<GEMM_GRID, 128, GSMEM16_BYTES>>>(b_out, out);
}

// round 17
// speedup vs baseline: 1.0547x; 1.0375x over previous
#include <cuda_runtime.h>
#include <cuda_fp16.h>

#define B_     32
#define N_     577
#define L_     576
#define DIM_   512
#define HEADS_ 8
#define NDIM_  16
#define M_ROWS (B_ * N_)   // 18464
#define ECH 16
#define ECL 36
#define VTP 640

// -------- scratch (device globals; __half arrays 16B-aligned for cp.async) --------
// RULE: NEVER pass these as host-side kernel arguments (host shadow symbol!).
__device__ __align__(16) __half g_xm16[(size_t)B_ * N_ * DIM_];
__device__ __align__(16) __half g_qk16[(size_t)B_ * N_ * 1024];
__device__ float g_v [(size_t)B_ * N_ * 512];
__device__ __align__(16) __half g_vt16[(size_t)B_ * 512 * VTP];
__device__ __align__(16) __half g_ao16[(size_t)B_ * N_ * 512];
__device__ float g_cq[NDIM_][2 * DIM_];
__device__ float g_cc[NDIM_][2 * DIM_];
__device__ __align__(16) __half g_wqk16[1024 * 512];
__device__ __align__(16) __half g_wv16 [512 * 512];
__device__ __align__(16) __half g_wo16 [512 * 512];

// ---------------- helpers ----------------
__device__ __forceinline__ unsigned f2tf(float x) {
    unsigned u;
    asm("cvt.rna.tf32.f32 %0, %1;" : "=r"(u) : "f"(x));
    return u;
}
__device__ __forceinline__ float f2tff(float x) { return __uint_as_float(f2tf(x)); }
__device__ __forceinline__ unsigned pack2(float x, float y) {
    __half2 h = __floats2half2_rn(x, y);
    return *reinterpret_cast<unsigned*>(&h);
}
__device__ __forceinline__ void mma16(float* c, const unsigned* a, unsigned b0, unsigned b1) {
    asm volatile(
        "mma.sync.aligned.m16n8k16.row.col.f32.f16.f16.f32 "
        "{%0,%1,%2,%3},{%4,%5,%6,%7},{%8,%9},{%0,%1,%2,%3};"
        : "+f"(c[0]), "+f"(c[1]), "+f"(c[2]), "+f"(c[3])
        : "r"(a[0]), "r"(a[1]), "r"(a[2]), "r"(a[3]), "r"(b0), "r"(b1));
}
#define LDSM4(r0, r1, r2, r3, addr)                                              \
    asm volatile("ldmatrix.sync.aligned.m8n8.x4.shared.b16 {%0,%1,%2,%3}, [%4];" \
                 : "=r"(r0), "=r"(r1), "=r"(r2), "=r"(r3) : "r"(addr))

__device__ __forceinline__ unsigned s2u(const void* p) {
    return (unsigned)__cvta_generic_to_shared(p);
}
__device__ __forceinline__ void cp16(unsigned dst, const void* src, int srcsz) {
    asm volatile("cp.async.cg.shared.global [%0], [%1], 16, %2;"
                 :: "r"(dst), "l"(src), "r"(srcsz));
}
#define CP_COMMIT() asm volatile("cp.async.commit_group;")
#define CP_WAIT1()  asm volatile("cp.async.wait_group 1;")
#define CP_WAIT2()  asm volatile("cp.async.wait_group 2;")

__device__ __forceinline__ float pow36f(float q) {
    float q2 = q * q, q4 = q2 * q2, q8 = q4 * q4, q16 = q8 * q8, q32 = q16 * q16;
    return q32 * q4;
}

// ================= Stage 0: EMA coefficients + fused weight prep =================
__global__ void coef_kernel(const float* __restrict__ delta, const float* __restrict__ alpha,
                            const float* __restrict__ beta,  const float* __restrict__ gamma) {
    int idx = blockIdx.x * blockDim.x + threadIdx.x;
    if (idx >= 2 * DIM_ * NDIM_) return;
    int d = idx / NDIM_;
    int n = idx % NDIM_;
    float p  = 1.f / (1.f + expf(-delta[idx]));
    float sa = 1.f / (1.f + expf(-alpha[idx]));
    g_cq[n][d] = 1.f - p * sa;
    g_cc[n][d] = p * beta[idx] * gamma[idx] * 0.25f;
}

__global__ void tcvt_all(const float* __restrict__ wqk, const float* __restrict__ wv,
                         const float* __restrict__ wo) {
    int i = blockIdx.x * 256 + threadIdx.x;
    if (i < 1024 * 512) {
        int n = i >> 9, k = i & 511;
        g_wqk16[i] = __float2half_rn(wqk[(size_t)k * 1024 + n]);
    } else if (i < 1024 * 512 + 512 * 512) {
        int j = i - 1024 * 512;
        int n = j >> 9, k = j & 511;
        g_wv16[j] = __float2half_rn(wv[(size_t)k * 512 + n]);
    } else if (i < 1024 * 512 + 2 * 512 * 512) {
        int j = i - 1024 * 512 - 512 * 512;
        int n = j >> 9, k = j & 511;
        g_wo16[j] = __float2half_rn(wo[(size_t)k * 512 + n]);
    }
}

// ================= Stage 1: fused bidirectional EMA (validated) =========
#define ESM_STATE (ECH * NDIM_ * 17)
#define ESM_Y     (ECL * ECH * 17)
#define ESM_TOTAL (2 * ESM_STATE + ESM_Y)

__global__ void __launch_bounds__(256, 2) ema_fused(const float* __restrict__ x,
                                                    const float* __restrict__ omega) {
    extern __shared__ float es[];
    float* Sf = es;
    float* Sb = es + ESM_STATE;
    float* Ys = es + 2 * ESM_STATE;

    int tid = threadIdx.x;
    int c = tid >> 4, dl = tid & 15;
    int d = blockIdx.x * 16 + dl;
    int b = blockIdx.z;
    const float* xb = x + (size_t)b * N_ * DIM_ + d;
    __half*      yb = g_xm16 + (size_t)b * N_ * DIM_ + d;
    int t0 = c * ECL;

    if (tid < 16) yb[0] = __float2half_rn(xb[0]);

    float q[NDIM_], q2[NDIM_], s[NDIM_];
#pragma unroll
    for (int n = 0; n < NDIM_; n++) { q[n] = g_cq[n][d]; s[n] = 0.f; }
#pragma unroll 4
    for (int tl = 0; tl < ECL; tl++) {
        float xv = xb[(size_t)(t0 + tl + 1) * DIM_];
#pragma unroll
        for (int n = 0; n < NDIM_; n++) s[n] = q[n] * s[n] + xv;
    }
#pragma unroll
    for (int n = 0; n < NDIM_; n++) Sf[(c * NDIM_ + n) * 17 + dl] = s[n];

#pragma unroll
    for (int n = 0; n < NDIM_; n++) { q2[n] = g_cq[n][d + DIM_]; s[n] = 0.f; }
#pragma unroll 4
    for (int tl = ECL - 1; tl >= 0; tl--) {
        float xv = xb[(size_t)(t0 + tl + 1) * DIM_];
#pragma unroll
        for (int n = 0; n < NDIM_; n++) s[n] = q2[n] * s[n] + xv;
    }
#pragma unroll
    for (int n = 0; n < NDIM_; n++) Sb[(c * NDIM_ + n) * 17 + dl] = s[n];
    __syncthreads();

    float cc[NDIM_];
#pragma unroll
    for (int n = 0; n < NDIM_; n++) {
        float qp = pow36f(q[n]);
        float Sin = 0.f;
        for (int cp = 0; cp < c; cp++)
            Sin = qp * Sin + Sf[(cp * NDIM_ + n) * 17 + dl];
        s[n] = Sin;
        cc[n] = g_cc[n][d];
    }
#pragma unroll 4
    for (int tl = 0; tl < ECL; tl++) {
        float xv = xb[(size_t)(t0 + tl + 1) * DIM_];
        float a[4] = {0.f, 0.f, 0.f, 0.f};
#pragma unroll
        for (int n = 0; n < NDIM_; n++) { s[n] = q[n] * s[n] + xv; a[n >> 2] += cc[n] * s[n]; }
        Ys[tl * (ECH * 17) + c * 17 + dl] = (a[0] + a[1]) + (a[2] + a[3]);
    }

#pragma unroll
    for (int n = 0; n < NDIM_; n++) {
        float qp = pow36f(q2[n]);
        float Sin = 0.f;
        for (int cp = ECH - 1; cp > c; cp--)
            Sin = qp * Sin + Sb[(cp * NDIM_ + n) * 17 + dl];
        s[n] = Sin;
        cc[n] = g_cc[n][d + DIM_];
    }
    float om = omega[d];
#pragma unroll 4
    for (int tl = ECL - 1; tl >= 0; tl--) {
        float xv = xb[(size_t)(t0 + tl + 1) * DIM_];
        float a[4] = {0.f, 0.f, 0.f, 0.f};
#pragma unroll
        for (int n = 0; n < NDIM_; n++) { s[n] = q2[n] * s[n] + xv; a[n >> 2] += cc[n] * s[n]; }
        float u = Ys[tl * (ECH * 17) + c * 17 + dl]
                + ((a[0] + a[1]) + (a[2] + a[3])) + xv * om;
        yb[(size_t)(t0 + tl + 1) * DIM_] = __float2half_rn(u / (1.f + __expf(-u)));
    }
}

// ======= fp16 GEMM: 128x128 tile, 3-stage cp.async, ldmatrix frag loads =====
#define AWSTR 20
#define TSLAB (128 * AWSTR)
#define GSMEM16_BYTES (6 * TSLAB * 4)

__device__ __forceinline__ void gemm16_tile(const __half* __restrict__ A,
                                            const __half* __restrict__ Bw, int M,
                                            __half* __restrict__ C16, int c16s,
                                            float* __restrict__ C32, int c32s,
                                            const float* __restrict__ bias, bool rnd,
                                            int bnb, int bmb) {
    extern __shared__ unsigned gsw[];
    unsigned as_u = s2u(gsw);
    unsigned bs_u = as_u + 3 * TSLAB * 4;

    int tid = threadIdx.x, lane = tid & 31, w = tid >> 5;
    int gr = lane >> 2, tg = lane & 3;
    int wm = w & 1, wn = w >> 1;
    int bm = bmb * 128, bn = bnb * 128;

    // ldmatrix per-lane row/col (verified conflict-free for stride 20)
    int arow = wm * 64 + ((lane >> 3) & 1) * 8 + (lane & 7);   // + mt*16
    int acol = ((lane >> 4) & 1) * 4;                          // + kk*8
    int brow = wn * 64 + ((lane >> 4) & 1) * 8 + (lane & 7);   // + p*16
    int bcol = ((lane >> 3) & 1) * 4;                          // + kk*8

#define G16_ISSUE(s)                                                                   \
    do {                                                                               \
        int _buf = (s) % 3, _k0 = (s) * 32;                                            \
        unsigned _ad = as_u + (unsigned)(_buf * TSLAB * 4);                            \
        unsigned _bd = bs_u + (unsigned)(_buf * TSLAB * 4);                            \
        _Pragma("unroll")                                                              \
        for (int it = 0; it < 4; it++) {                                               \
            int idx = tid + it * 128;                                                  \
            int row = idx >> 2, cq = idx & 3;                                          \
            bool ok = (bm + row < M);                                                  \
            const __half* src = A + (size_t)(ok ? bm + row : 0) * 512 + _k0 + cq * 8;  \
            cp16(_ad + (unsigned)((row * AWSTR + cq * 4) * 4), src, ok ? 16 : 0);      \
        }                                                                              \
        _Pragma("unroll")                                                              \
        for (int it = 0; it < 4; it++) {                                               \
            int idx = tid + it * 128;                                                  \
            int row = idx >> 2, cq = idx & 3;                                          \
            cp16(_bd + (unsigned)((row * AWSTR + cq * 4) * 4),                         \
                 Bw + (size_t)(bn + row) * 512 + _k0 + cq * 8, 16);                    \
        }                                                                              \
    } while (0)

    G16_ISSUE(0); CP_COMMIT();
    G16_ISSUE(1); CP_COMMIT();

    float acc[4][8][4];
#pragma unroll
    for (int mt = 0; mt < 4; mt++)
#pragma unroll
        for (int nt = 0; nt < 8; nt++)
#pragma unroll
            for (int e = 0; e < 4; e++) acc[mt][nt][e] = 0.f;

    for (int s = 0; s < 16; s++) {
        if (s + 2 < 16) G16_ISSUE(s + 2);
        CP_COMMIT();
        CP_WAIT2();
        __syncthreads();
        unsigned ab = as_u + (unsigned)((s % 3) * TSLAB * 4);
        unsigned bb = bs_u + (unsigned)((s % 3) * TSLAB * 4);
#pragma unroll
        for (int kk = 0; kk < 2; kk++) {
            unsigned a[4][4];
#pragma unroll
            for (int mt = 0; mt < 4; mt++)
                LDSM4(a[mt][0], a[mt][1], a[mt][2], a[mt][3],
                      ab + (unsigned)((((arow + mt * 16) * AWSTR) + acol + kk * 8) * 4));
            unsigned bf[8][2];
#pragma unroll
            for (int p = 0; p < 4; p++)
                LDSM4(bf[2 * p][0], bf[2 * p][1], bf[2 * p + 1][0], bf[2 * p + 1][1],
                      bb + (unsigned)((((brow + p * 16) * AWSTR) + bcol + kk * 8) * 4));
#pragma unroll
            for (int nt = 0; nt < 8; nt++)
#pragma unroll
                for (int mt = 0; mt < 4; mt++) mma16(acc[mt][nt], a[mt], bf[nt][0], bf[nt][1]);
        }
        __syncthreads();
    }
#pragma unroll
    for (int mt = 0; mt < 4; mt++) {
        int r0 = bm + wm * 64 + mt * 16 + gr;
#pragma unroll
        for (int nt = 0; nt < 8; nt++) {
            int col = bn + wn * 64 + nt * 8 + 2 * tg;
            if (C16) {
                if (r0 < M)
                    *(unsigned*)(C16 + (size_t)r0 * c16s + col) =
                        pack2(acc[mt][nt][0], acc[mt][nt][1]);
                if (r0 + 8 < M)
                    *(unsigned*)(C16 + (size_t)(r0 + 8) * c16s + col) =
                        pack2(acc[mt][nt][2], acc[mt][nt][3]);
            } else {
                float bx = bias ? bias[col] : 0.f, by = bias ? bias[col + 1] : 0.f;
                float e0 = acc[mt][nt][0] + bx, e1 = acc[mt][nt][1] + by;
                float e2 = acc[mt][nt][2] + bx, e3 = acc[mt][nt][3] + by;
                if (rnd) { e0 = f2tff(e0); e1 = f2tff(e1); e2 = f2tff(e2); e3 = f2tff(e3); }
                if (r0 < M)     *(float2*)(C32 + (size_t)r0 * c32s + col)       = make_float2(e0, e1);
                if (r0 + 8 < M) *(float2*)(C32 + (size_t)(r0 + 8) * c32s + col) = make_float2(e2, e3);
            }
        }
    }
#undef G16_ISSUE
}

#define MB_ ((M_ROWS + 127) / 128)   // 145
#define GEMM_GRID 444

__global__ void __launch_bounds__(128, 3) gemm_qkv_tc() {
    for (int t = blockIdx.x; t < MB_ * 12; t += GEMM_GRID) {
        if (t < MB_ * 8)
            gemm16_tile(g_xm16, g_wqk16, M_ROWS, g_qk16, 1024, nullptr, 0, nullptr, false,
                        t & 7, t >> 3);
        else {
            int tt = t - MB_ * 8;
            gemm16_tile(g_xm16, g_wv16, M_ROWS, nullptr, 0, g_v, 512, nullptr, true,
                        tt & 3, tt >> 2);
        }
    }
}
__global__ void __launch_bounds__(128, 3) gemm_out_tc(const float* __restrict__ bias,
                                                      float* __restrict__ out) {
    for (int t = blockIdx.x; t < MB_ * 4; t += GEMM_GRID)
        gemm16_tile(g_ao16, g_wo16, M_ROWS, nullptr, 0, out, 512, bias, false, t & 3, t >> 2);
}

// ===== Stage 2b: V transpose  g_v fp32 -> g_vt16 fp16 [b][512][VTP] =====
__global__ void vt_kernel() {
    __shared__ float ts[32][33];
    int tx = threadIdx.x, ty = threadIdx.y;
    int n0 = blockIdx.x * 32, d0 = blockIdx.y * 32, b = blockIdx.z;
#pragma unroll
    for (int i = 0; i < 4; i++) {
        int n = n0 + ty + i * 8;
        ts[ty + i * 8][tx] = (n < N_) ? g_v[((size_t)b * N_ + n) * 512 + d0 + tx] : 0.f;
    }
    __syncthreads();
#pragma unroll
    for (int i = 0; i < 4; i++) {
        int d = d0 + ty + i * 8;
        g_vt16[((size_t)b * 512 + d) * VTP + n0 + tx] = __float2half_rn(ts[tx][ty + i * 8]);
    }
}

// ================= Stage 3: fp16 flash attention, ldmatrix frag loads =================
#define FKSTR 36
#define FKBUF (64 * FKSTR)
#define QROWS 96
#define NT_ ((N_ + 63) / 64)
#define FSMEM_BYTES (4 * FKBUF * 4 + (2 * N_ - 1) * 4)

__global__ void __launch_bounds__(192, 2) flash_attn_tc(const float* __restrict__ rb) {
    extern __shared__ unsigned fsw[];
    float* RBs = (float*)(fsw + 4 * FKBUF);
    unsigned ks_u = s2u(fsw);
    unsigned vs_u = ks_u + 2 * FKBUF * 4;

    int b = blockIdx.z, h = blockIdx.y;
    int i0 = blockIdx.x * QROWS;
    int tid = threadIdx.x, lane = tid & 31, w = tid >> 5;
    int gr = lane >> 2, tg = lane & 3;

    // ldmatrix per-lane row/col for K/V B-frags (stride 36: conflict-free)
    int frow = ((lane >> 4) & 1) * 8 + (lane & 7);   // + p*16
    int fcol = ((lane >> 3) & 1) * 4;                // + kk*8

    const __half* kb16 = g_qk16 + (size_t)b * N_ * 1024 + 512 + h * 64;
    const __half* vtb  = g_vt16 + ((size_t)b * 512 + h * 64) * VTP;
    const unsigned* qw = (const unsigned*)g_qk16 + (size_t)b * N_ * 512 + h * 32;

    for (int t = tid; t < 2 * N_ - 1; t += 192) RBs[t] = rb[t];

#define FL_ISSUE(jt)                                                                   \
    do {                                                                               \
        int _buf = (jt) & 1, _j0 = (jt) * 64;                                          \
        unsigned _kd = ks_u + (unsigned)(_buf * FKBUF * 4);                            \
        unsigned _vd = vs_u + (unsigned)(_buf * FKBUF * 4);                            \
        for (int idx = tid; idx < 512; idx += 192) {                                   \
            int j = idx >> 3, ch = idx & 7;                                            \
            bool ok = (_j0 + j < N_);                                                  \
            cp16(_kd + (unsigned)((j * FKSTR + ch * 4) * 4),                           \
                 kb16 + (size_t)(ok ? _j0 + j : 0) * 1024 + ch * 8, ok ? 16 : 0);      \
        }                                                                              \
        for (int idx = tid; idx < 512; idx += 192) {                                   \
            int dd = idx >> 3, ch = idx & 7;                                           \
            cp16(_vd + (unsigned)((dd * FKSTR + ch * 4) * 4),                          \
                 vtb + (size_t)dd * VTP + _j0 + ch * 8, 16);                           \
        }                                                                              \
    } while (0)

    unsigned qa[4][4];
    int rlo = i0 + w * 16 + gr;
    int rhi = rlo + 8;
#pragma unroll
    for (int kk = 0; kk < 4; kk++) {
        qa[kk][0] = (rlo < N_) ? qw[(size_t)rlo * 512 + kk * 8 + tg]     : 0u;
        qa[kk][1] = (rhi < N_) ? qw[(size_t)rhi * 512 + kk * 8 + tg]     : 0u;
        qa[kk][2] = (rlo < N_) ? qw[(size_t)rlo * 512 + kk * 8 + tg + 4] : 0u;
        qa[kk][3] = (rhi < N_) ? qw[(size_t)rhi * 512 + kk * 8 + tg + 4] : 0u;
    }

    FL_ISSUE(0); CP_COMMIT();

    float o[8][4], ob[8][4];
#pragma unroll
    for (int nt = 0; nt < 8; nt++)
#pragma unroll
        for (int e = 0; e < 4; e++) { o[nt][e] = 0.f; ob[nt][e] = 0.f; }
    float mlo = -1e30f, mhi = -1e30f, zlo = 0.f, zhi = 0.f;

    for (int jt = 0; jt < NT_; jt++) {
        int j0 = jt * 64;
        bool full = (j0 + 64 <= N_);
        __syncthreads();
        if (jt + 1 < NT_) FL_ISSUE(jt + 1);
        CP_COMMIT();
        CP_WAIT1();
        __syncthreads();
        unsigned kbuf = ks_u + (unsigned)((jt & 1) * FKBUF * 4);
        unsigned vbuf = vs_u + (unsigned)((jt & 1) * FKBUF * 4);

        // ---- S = (Q @ K^T) * 0.125 ----
        float s[8][4];
#pragma unroll
        for (int nt = 0; nt < 8; nt++)
#pragma unroll
            for (int e = 0; e < 4; e++) s[nt][e] = 0.f;
#pragma unroll
        for (int kk = 0; kk < 4; kk++) {
            unsigned kbf[8][2];
#pragma unroll
            for (int p = 0; p < 4; p++)
                LDSM4(kbf[2 * p][0], kbf[2 * p][1], kbf[2 * p + 1][0], kbf[2 * p + 1][1],
                      kbuf + (unsigned)((((p * 16 + frow) * FKSTR) + fcol + kk * 8) * 4));
#pragma unroll
            for (int nt = 0; nt < 8; nt++)
                mma16(s[nt], qa[kk], kbf[nt][0], kbf[nt][1]);
        }
#pragma unroll
        for (int nt = 0; nt < 8; nt++)
#pragma unroll
            for (int e = 0; e < 4; e++) s[nt][e] *= 0.125f;

        // ---- online softmax; P packed straight into fp16 A-frags ----
        float tlo = -1e30f, thi = -1e30f;
#pragma unroll
        for (int nt = 0; nt < 8; nt++) {
            int col = j0 + nt * 8 + 2 * tg;
            if (full || col < N_)     { tlo = fmaxf(tlo, s[nt][0]); thi = fmaxf(thi, s[nt][2]); }
            if (full || col + 1 < N_) { tlo = fmaxf(tlo, s[nt][1]); thi = fmaxf(thi, s[nt][3]); }
        }
#pragma unroll
        for (int off = 1; off <= 2; off <<= 1) {
            tlo = fmaxf(tlo, __shfl_xor_sync(0xffffffffu, tlo, off));
            thi = fmaxf(thi, __shfl_xor_sync(0xffffffffu, thi, off));
        }
        float mlon = fmaxf(mlo, tlo), mhin = fmaxf(mhi, thi);
        float sclo = __expf(mlo - mlon), schi = __expf(mhi - mhin);
        float psl = 0.f, psh = 0.f;
        unsigned pp[8][2];
#pragma unroll
        for (int nt = 0; nt < 8; nt++) {
            int col = j0 + nt * 8 + 2 * tg;
            float p0 = (full || col     < N_) ? __expf(s[nt][0] - mlon) : 0.f;
            float p1 = (full || col + 1 < N_) ? __expf(s[nt][1] - mlon) : 0.f;
            float p2 = (full || col     < N_) ? __expf(s[nt][2] - mhin) : 0.f;
            float p3 = (full || col + 1 < N_) ? __expf(s[nt][3] - mhin) : 0.f;
            psl += p0 + p1; psh += p2 + p3;
            o[nt][0] *= sclo; o[nt][1] *= sclo;
            o[nt][2] *= schi; o[nt][3] *= schi;
            pp[nt][0] = pack2(p0, p1);
            pp[nt][1] = pack2(p2, p3);
        }
#pragma unroll
        for (int off = 1; off <= 2; off <<= 1) {
            psl += __shfl_xor_sync(0xffffffffu, psl, off);
            psh += __shfl_xor_sync(0xffffffffu, psh, off);
        }
        zlo = zlo * sclo + psl;  zhi = zhi * schi + psh;
        mlo = mlon;  mhi = mhin;

        // ---- O += P @ V ;  Ob += bias @ V ----
#pragma unroll
        for (int kk = 0; kk < 4; kk++) {
            unsigned pa[4] = { pp[2 * kk][0], pp[2 * kk][1],
                               pp[2 * kk + 1][0], pp[2 * kk + 1][1] };
            unsigned ba[4];
            int jb = j0 + kk * 16 + 2 * tg;
            float b00 = (rlo < N_ && jb     < N_) ? RBs[576 + jb - rlo]     : 0.f;
            float b01 = (rlo < N_ && jb + 1 < N_) ? RBs[576 + jb + 1 - rlo] : 0.f;
            float b10 = (rhi < N_ && jb     < N_) ? RBs[576 + jb - rhi]     : 0.f;
            float b11 = (rhi < N_ && jb + 1 < N_) ? RBs[576 + jb + 1 - rhi] : 0.f;
            float b20 = (rlo < N_ && jb + 8 < N_) ? RBs[576 + jb + 8 - rlo] : 0.f;
            float b21 = (rlo < N_ && jb + 9 < N_) ? RBs[576 + jb + 9 - rlo] : 0.f;
            float b30 = (rhi < N_ && jb + 8 < N_) ? RBs[576 + jb + 8 - rhi] : 0.f;
            float b31 = (rhi < N_ && jb + 9 < N_) ? RBs[576 + jb + 9 - rhi] : 0.f;
            ba[0] = pack2(b00, b01); ba[1] = pack2(b10, b11);
            ba[2] = pack2(b20, b21); ba[3] = pack2(b30, b31);
            unsigned vbf[8][2];
#pragma unroll
            for (int p = 0; p < 4; p++)
                LDSM4(vbf[2 * p][0], vbf[2 * p][1], vbf[2 * p + 1][0], vbf[2 * p + 1][1],
                      vbuf + (unsigned)((((p * 16 + frow) * FKSTR) + fcol + kk * 8) * 4));
#pragma unroll
            for (int nt = 0; nt < 8; nt++) {
                mma16(o[nt],  pa, vbf[nt][0], vbf[nt][1]);
                mma16(ob[nt], ba, vbf[nt][0], vbf[nt][1]);
            }
        }
    }

    float izlo = 1.f / zlo, izhi = 1.f / zhi;
#pragma unroll
    for (int nt = 0; nt < 8; nt++) {
        int col = h * 64 + nt * 8 + 2 * tg;
        if (rlo < N_)
            *(unsigned*)(g_ao16 + ((size_t)b * N_ + rlo) * 512 + col) =
                pack2(o[nt][0] * izlo + ob[nt][0], o[nt][1] * izlo + ob[nt][1]);
        if (rhi < N_)
            *(unsigned*)(g_ao16 + ((size_t)b * N_ + rhi) * 512 + col) =
                pack2(o[nt][2] * izhi + ob[nt][2], o[nt][3] * izhi + ob[nt][3]);
    }
#undef FL_ISSUE
}

// ================= launch =================
extern "C" void kernel_launch(void* const* d_in, const int* in_sizes, int n_in,
                              void* d_out, int out_size) {
    const float* x         = (const float*)d_in[0];
    const float* W_qk      = (const float*)d_in[1];
    const float* W_v       = (const float*)d_in[2];
    const float* W_out     = (const float*)d_in[3];
    const float* b_out     = (const float*)d_in[4];
    const float* rel_bias  = (const float*)d_in[5];
    const float* ema_delta = (const float*)d_in[6];
    const float* ema_alpha = (const float*)d_in[7];
    const float* ema_beta  = (const float*)d_in[8];
    const float* ema_gamma = (const float*)d_in[9];
    const float* ema_omega = (const float*)d_in[10];
    float* out = (float*)d_out;

    static int attr_set = 0;
    if (!attr_set) {
        cudaFuncSetAttribute(ema_fused, cudaFuncAttributeMaxDynamicSharedMemorySize,
                             ESM_TOTAL * (int)sizeof(float));
        cudaFuncSetAttribute(gemm_qkv_tc, cudaFuncAttributeMaxDynamicSharedMemorySize, GSMEM16_BYTES);
        cudaFuncSetAttribute(gemm_out_tc, cudaFuncAttributeMaxDynamicSharedMemorySize, GSMEM16_BYTES);
        cudaFuncSetAttribute(flash_attn_tc, cudaFuncAttributeMaxDynamicSharedMemorySize, FSMEM_BYTES);
        attr_set = 1;
    }

    coef_kernel<<<(2 * DIM_ * NDIM_ + 255) / 256, 256>>>(ema_delta, ema_alpha, ema_beta, ema_gamma);
    tcvt_all<<<(1024 * 512 + 2 * 512 * 512 + 255) / 256, 256>>>(W_qk, W_v, W_out);
    ema_fused<<<dim3(DIM_ / 16, 1, B_), 256, ESM_TOTAL * sizeof(float)>>>(x, ema_omega);

    gemm_qkv_tc<<<GEMM_GRID, 128, GSMEM16_BYTES>>>();
    vt_kernel<<<dim3(VTP / 32, 16, B_), dim3(32, 8)>>>();

    flash_attn_tc<<<dim3((N_ + QROWS - 1) / QROWS, HEADS_, B_), 192, FSMEM_BYTES>>>(rel_bias);

    gemm_out_tc<<<GEMM_GRID, 128, GSMEM16_BYTES>>>(b_out, out);
}